// round 6
// baseline (speedup 1.0000x reference)
#include <cuda_runtime.h>

#define NN 8
#define CC 64
#define HH 128
#define WW 128
#define TAPS 9
#define STEPS 10
#define EPSV 1e-5f

// Scratch: normalized weights [n,9,h,w] and ping-pong x buffer [n,c,h,w]
__device__ float g_nw[(size_t)NN * TAPS * HH * WW];
__device__ float g_x[(size_t)NN * CC * HH * WW];

// ---------------------------------------------------------------------------
// Normalize: nw[n,t,h,w] = w[n,t,h,w] / (sum_t w + eps)
// ---------------------------------------------------------------------------
__global__ void mp_normalize_kernel(const float* __restrict__ wt) {
    int idx = blockIdx.x * blockDim.x + threadIdx.x;   // over N*H*W
    if (idx >= NN * HH * WW) return;
    int hw = idx % (HH * WW);
    int n  = idx / (HH * WW);
    const float* base = wt + (size_t)n * TAPS * HH * WW + hw;
    float v[TAPS];
    float s = EPSV;
#pragma unroll
    for (int t = 0; t < TAPS; t++) {
        v[t] = base[(size_t)t * HH * WW];
        s += v[t];
    }
    float inv = 1.0f / s;
    float* out = g_nw + (size_t)n * TAPS * HH * WW + hw;
#pragma unroll
    for (int t = 0; t < TAPS; t++)
        out[(size_t)t * HH * WW] = v[t] * inv;
}

// ---------------------------------------------------------------------------
// One step, smem row-band tiled.
// Block = 8 warps = output rows h0..h0+7 of one (n, channel-block of 8).
// Per channel: cooperatively load 10 input rows (with zero halo rows) into
// smem ONCE (vs 3x L2 re-reads before), sync, each warp computes its row
// from smem (LDS 29cyc vs L2 234cyc). w-halo via full-warp shuffle.
// Weights: 9 taps x 4 px in regs per thread (36 regs), reused for 8 channels.
// ---------------------------------------------------------------------------
#define SW 4
#define RPB 8                 // rows per block (= warps per block)
#define TILE_H (RPB + 2)      // 10 rows incl halo
#define CBLKS 8
#define CPB (CC / CBLKS)      // 8 channels per block

__global__ void __launch_bounds__(256, 4) mp_step_kernel(
    const float* __restrict__ xin, float* __restrict__ xout)
{
    __shared__ float tile[TILE_H][WW];   // 10 x 128 floats = 5 KB

    const int tid  = threadIdx.x;
    const int wid  = tid >> 5;           // 0..7  -> row within band
    const int lane = tid & 31;           // 0..31 -> 4-px strip
    const int w0   = lane * SW;

    int b  = blockIdx.x;                 // 1024 blocks
    const int hb = b & 15;  b >>= 4;     // 16 row-bands
    const int n  = b & 7;   b >>= 3;     // 8 batches
    const int cb = b;                    // 8 channel blocks
    const int h0 = hb * RPB;
    const int h  = h0 + wid;

    // Per-thread weights for its (h, w0..w0+3): 9 taps x 4 px = 36 regs
    float wv[TAPS][SW];
#pragma unroll
    for (int t = 0; t < TAPS; t++) {
        float4 a = *(const float4*)(g_nw + (((size_t)n * TAPS + t) * HH + h) * WW + w0);
        wv[t][0] = a.x; wv[t][1] = a.y; wv[t][2] = a.z; wv[t][3] = a.w;
    }

    const size_t plane = (size_t)HH * WW;
    const float* xb = xin  + ((size_t)n * CC + cb * CPB) * plane;
    float*       ob = xout + ((size_t)n * CC + cb * CPB) * plane + (size_t)h * WW + w0;

    for (int c = 0; c < CPB; c++) {
        if (c) __syncthreads();          // prior compute done before overwrite

        // Cooperative load: 10 rows x 32 float4 = 320 slots over 256 threads
        const float* src = xb + (size_t)c * plane;
#pragma unroll
        for (int i = tid; i < TILE_H * 32; i += 256) {
            int r = i >> 5;              // tile row 0..9
            int q = (i & 31) * 4;        // float4 col
            int g = h0 - 1 + r;          // global row -1..128
            float4 val = (g >= 0 && g < HH)
                       ? *(const float4*)(src + (size_t)g * WW + q)
                       : make_float4(0.f, 0.f, 0.f, 0.f);
            *(float4*)&tile[r][q] = val;
        }
        __syncthreads();

        float acc[SW];
#pragma unroll
        for (int k = 0; k < SW; k++) acc[k] = 0.f;

#pragma unroll
        for (int di = 0; di < 3; di++) {
            // tile row wid+di == input row h-1+di (halo rows pre-zeroed)
            float4 A = *(const float4*)&tile[wid + di][w0];
            float v[SW + 2];
            v[1] = A.x; v[2] = A.y; v[3] = A.z; v[4] = A.w;
            // w-halo from neighbor lanes (warp spans the full 128-px row)
            float l = __shfl_up_sync  (0xffffffffu, v[SW], 1);
            float r = __shfl_down_sync(0xffffffffu, v[1],  1);
            v[0]      = (lane == 0)  ? 0.f : l;
            v[SW + 1] = (lane == 31) ? 0.f : r;

            const float* wL = wv[di * 3 + 0];
            const float* wC = wv[di * 3 + 1];
            const float* wR = wv[di * 3 + 2];
#pragma unroll
            for (int k = 0; k < SW; k++)
                acc[k] += wL[k] * v[k] + wC[k] * v[k + 1] + wR[k] * v[k + 2];
        }
        *(float4*)(ob + (size_t)c * plane) = make_float4(acc[0], acc[1], acc[2], acc[3]);
    }
}

// ---------------------------------------------------------------------------
// kernel_launch: normalize once, then 10 ping-pong steps ending in d_out.
// ---------------------------------------------------------------------------
extern "C" void kernel_launch(void* const* d_in, const int* in_sizes, int n_in,
                              void* d_out, int out_size) {
    (void)in_sizes; (void)n_in; (void)out_size;
    const float* input  = (const float*)d_in[0];
    const float* weight = (const float*)d_in[1];
    float* out = (float*)d_out;

    float* xscr = nullptr;
    cudaGetSymbolAddress((void**)&xscr, g_x);

    const int threads = 256;
    {
        int total = NN * HH * WW;
        mp_normalize_kernel<<<(total + threads - 1) / threads, threads>>>(weight);
    }

    const int blocks = (HH / RPB) * NN * CBLKS;   // 16*8*8 = 1024

    // 10 hops: in -> g_x -> out -> g_x -> out ... (step 10 ends in d_out)
    const float* src = input;
    for (int k = 1; k <= STEPS; k++) {
        float* dst = (k & 1) ? xscr : out;
        mp_step_kernel<<<blocks, threads>>>(src, dst);
        src = dst;
    }
}

// round 7
// speedup vs baseline: 1.1551x; 1.1551x over previous
#include <cuda_runtime.h>

#define NN 8
#define CC 64
#define HH 128
#define WW 128
#define TAPS 9
#define STEPS 10
#define EPSV 1e-5f

// Scratch: normalized weights [n,9,h,w] and ping-pong x buffer [n,c,h,w]
__device__ float g_nw[(size_t)NN * TAPS * HH * WW];
__device__ float g_x[(size_t)NN * CC * HH * WW];

// ---------------------------------------------------------------------------
// Normalize: nw[n,t,h,w] = w[n,t,h,w] / (sum_t w + eps)
// ---------------------------------------------------------------------------
__global__ void mp_normalize_kernel(const float* __restrict__ wt) {
    int idx = blockIdx.x * blockDim.x + threadIdx.x;   // over N*H*W
    if (idx >= NN * HH * WW) return;
    int hw = idx % (HH * WW);
    int n  = idx / (HH * WW);
    const float* base = wt + (size_t)n * TAPS * HH * WW + hw;
    float v[TAPS];
    float s = EPSV;
#pragma unroll
    for (int t = 0; t < TAPS; t++) {
        v[t] = base[(size_t)t * HH * WW];
        s += v[t];
    }
    float inv = 1.0f / s;
    float* out = g_nw + (size_t)n * TAPS * HH * WW + hw;
#pragma unroll
    for (int t = 0; t < TAPS; t++)
        out[(size_t)t * HH * WW] = v[t] * inv;
}

// ---------------------------------------------------------------------------
// One step, di-OUTER / channel-INNER (round-6 smem variant regressed; this
// reverts to the barrier-free round-5 dataflow but widens ILP):
//   for di in {0,1,2}:  load the 3 taps of this row (12 regs live, not 36);
//     for c in 0..7:    one independent LDG.128 + 2 SHFL + 12 FMA chain
// acc[8][4] persists in registers (32 regs); stores once at the end.
// 8 independent chains per phase -> MLP ~6-8 vs ~3 before, same instr count,
// same 64-reg / 4-block occupancy envelope.
// Thread = (4-px strip, 8 channels); warp spans one full 128-px row, so
// w-halo comes from neighbor lanes via shuffle (lanes 0/31 = image border).
// ---------------------------------------------------------------------------
#define SW 4
#define STRIPS (WW / SW)  // 32 = warp width
#define CBLKS 8
#define CPB (CC / CBLKS)  // 8 channels per thread

__global__ void __launch_bounds__(256, 4) mp_step_kernel(
    const float* __restrict__ xin, float* __restrict__ xout)
{
    int tid = blockIdx.x * blockDim.x + threadIdx.x;
    // total = CBLKS*NN*HH*STRIPS = 262144; grid sized exactly, no tail check
    const int s  = tid & (STRIPS - 1);    // lane
    int t1 = tid >> 5;
    const int h  = t1 & (HH - 1);  t1 >>= 7;
    const int n  = t1 & (NN - 1);
    const int cb = t1 >> 3;
    const int w0 = s * SW;

    const size_t plane = (size_t)HH * WW;
    const float* xb = xin  + ((size_t)n * CC + cb * CPB) * plane + (size_t)h * WW + w0;
    float*       ob = xout + ((size_t)n * CC + cb * CPB) * plane + (size_t)h * WW + w0;
    const float* wb = g_nw + ((size_t)n * TAPS * HH + h) * WW + w0;

    float acc[CPB][SW];
#pragma unroll
    for (int c = 0; c < CPB; c++)
#pragma unroll
        for (int k = 0; k < SW; k++) acc[c][k] = 0.f;

#pragma unroll
    for (int di = 0; di < 3; di++) {
        // Uniform-per-warp border check (h identical across the warp)
        if ((di == 0 && h == 0) || (di == 2 && h == HH - 1)) continue;

        // 3 taps of this kernel row: 12 weight regs live at a time
        const float4 wA = *(const float4*)(wb + (size_t)(di * 3 + 0) * plane);
        const float4 wB = *(const float4*)(wb + (size_t)(di * 3 + 1) * plane);
        const float4 wC = *(const float4*)(wb + (size_t)(di * 3 + 2) * plane);

        const float* rowb = xb + ((long)di - 1) * WW;
#pragma unroll
        for (int c = 0; c < CPB; c++) {
            float4 A = *(const float4*)(rowb + (size_t)c * plane);
            // w-halo from neighbor lanes
            float l = __shfl_up_sync  (0xffffffffu, A.w, 1);
            float r = __shfl_down_sync(0xffffffffu, A.x, 1);
            float v0 = (s == 0)          ? 0.f : l;
            float v5 = (s == STRIPS - 1) ? 0.f : r;

            acc[c][0] += wA.x * v0  + wB.x * A.x + wC.x * A.y;
            acc[c][1] += wA.y * A.x + wB.y * A.y + wC.y * A.z;
            acc[c][2] += wA.z * A.y + wB.z * A.z + wC.z * A.w;
            acc[c][3] += wA.w * A.z + wB.w * A.w + wC.w * v5;
        }
    }

#pragma unroll
    for (int c = 0; c < CPB; c++)
        *(float4*)(ob + (size_t)c * plane) =
            make_float4(acc[c][0], acc[c][1], acc[c][2], acc[c][3]);
}

// ---------------------------------------------------------------------------
// kernel_launch: normalize once, then 10 ping-pong steps ending in d_out.
// ---------------------------------------------------------------------------
extern "C" void kernel_launch(void* const* d_in, const int* in_sizes, int n_in,
                              void* d_out, int out_size) {
    (void)in_sizes; (void)n_in; (void)out_size;
    const float* input  = (const float*)d_in[0];
    const float* weight = (const float*)d_in[1];
    float* out = (float*)d_out;

    float* xscr = nullptr;
    cudaGetSymbolAddress((void**)&xscr, g_x);

    const int threads = 256;
    {
        int total = NN * HH * WW;
        mp_normalize_kernel<<<(total + threads - 1) / threads, threads>>>(weight);
    }

    const int totalStep = CBLKS * NN * HH * STRIPS;  // 262144
    const int blocks = totalStep / threads;          // 1024

    // 10 hops: in -> g_x -> out -> g_x -> out ... (step 10 ends in d_out)
    const float* src = input;
    for (int k = 1; k <= STEPS; k++) {
        float* dst = (k & 1) ? xscr : out;
        mp_step_kernel<<<blocks, threads>>>(src, dst);
        src = dst;
    }
}